// round 6
// baseline (speedup 1.0000x reference)
#include <cuda_runtime.h>
#include <stdint.h>

#define N_POINTS 1200000
#define NFEAT 5
#define GXD 400
#define GYD 400
#define NCELLS (GXD*GYD)          // 160000
#define NCELLS_PAD 163840         // 40 * 4096
#define MAXV 60000
#define MAXP 32
#define OUT_COORD_OFF (MAXV*MAXP*NFEAT)        // 9,600,000
#define OUT_NUM_OFF   (OUT_COORD_OFF + MAXV*3) // 9,780,000
#define SCAN_BLOCKS 40
#define CELLS_PER_BLOCK 4096       // 1024 threads * 4 cells

// zeroed each run: [0,NCELLS_PAD) = per-cell counts, then SCAN_BLOCKS lookback states
__device__ unsigned g_dyn[NCELLS_PAD + SCAN_BLOCKS];
__device__ int      g_cellvox[NCELLS_PAD];
__device__ int      g_totvox;
// slot[cell][rank] = two float4: {x,y,z,idx_bits},{f3,f4,-,-}  (32B contiguous)
__device__ float4   g_slot[(size_t)NCELLS * MAXP * 2];

// ---------------- assign: point -> cell, atomic rank, stage full point ----------------
__global__ void k_assign(const float* __restrict__ pts) {
    int i = blockIdx.x * blockDim.x + threadIdx.x;
    if (i >= N_POINTS) return;
    const float* p = pts + (size_t)i * NFEAT;
    float x = p[0], y = p[1], z = p[2], f3 = p[3], f4 = p[4];
    // exact: (v+50)*4 == (v-(-50))/0.25 ; (v+5)*0.125 == (v-(-5))/8
    int cx = (int)floorf((x + 50.0f) * 4.0f);
    int cy = (int)floorf((y + 50.0f) * 4.0f);
    int cz = (int)floorf((z + 5.0f) * 0.125f);
    if (cx >= 0 && cx < GXD && cy >= 0 && cy < GYD && cz == 0) {
        int cell = cy * GXD + cx;
        unsigned r = atomicAdd(&g_dyn[cell], 1u);
        if (r < MAXP) {
            size_t s = ((size_t)cell * MAXP + r) * 2;
            g_slot[s]     = make_float4(x, y, z, __int_as_float(i));
            g_slot[s + 1] = make_float4(f3, f4, 0.0f, 0.0f);
        }
    }
}

// ---------------- scan: single-wave decoupled lookback, warp-parallel ----------------
__global__ void __launch_bounds__(1024, 1) k_scan() {
    __shared__ int wsum[32];
    __shared__ unsigned s_prefix;
    unsigned* state = g_dyn + NCELLS_PAD;
    const int t = threadIdx.x, b = blockIdx.x;
    const int lane = t & 31, w = t >> 5;
    const int c0 = b * CELLS_PER_BLOCK + t * 4;

    uint4 c4 = *(const uint4*)&g_dyn[c0];
    int o0 = c4.x ? 1 : 0, o1 = c4.y ? 1 : 0, o2 = c4.z ? 1 : 0, o3 = c4.w ? 1 : 0;
    int s = o0 + o1 + o2 + o3;

    // warp inclusive scan of per-thread sums
    int x = s;
    #pragma unroll
    for (int o = 1; o < 32; o <<= 1) {
        int v = __shfl_up_sync(0xffffffffu, x, o);
        if (lane >= o) x += v;
    }
    if (lane == 31) wsum[w] = x;
    __syncthreads();
    if (w == 0) {
        int y = wsum[lane];
        #pragma unroll
        for (int o = 1; o < 32; o <<= 1) {
            int v = __shfl_up_sync(0xffffffffu, y, o);
            if (lane >= o) y += v;
        }
        wsum[lane] = y;   // inclusive scan of warp sums
    }
    __syncthreads();
    int incl = x + (w ? wsum[w - 1] : 0);
    unsigned agg = (unsigned)wsum[31];

    // publish aggregate (payload carried in the atomic word; no fence needed)
    if (t == 0) {
        if (b == 0) atomicExch(&state[0], (2u << 30) | agg);
        else        atomicExch(&state[b], (1u << 30) | agg);
    }
    // warp 0: parallel lookback over 32 predecessors per round
    if (w == 0) {
        if (b == 0) { if (lane == 0) s_prefix = 0; }
        else {
            unsigned run = 0;
            int j = b - 1 - lane;
            for (;;) {
                unsigned sv = (j >= 0) ? *(volatile unsigned*)&state[j] : (2u << 30);
                unsigned flag = sv >> 30;
                if (__all_sync(0xffffffffu, flag != 0u)) {
                    unsigned pm = __ballot_sync(0xffffffffu, flag >= 2u);
                    int fp = (pm != 0u) ? (__ffs(pm) - 1) : -1;
                    unsigned contrib = (fp < 0 || lane <= fp) ? (sv & 0x3FFFFFFFu) : 0u;
                    #pragma unroll
                    for (int o = 16; o; o >>= 1)
                        contrib += __shfl_down_sync(0xffffffffu, contrib, o);
                    contrib = __shfl_sync(0xffffffffu, contrib, 0);
                    run += contrib;
                    if (fp >= 0) break;
                    j -= 32;
                }
            }
            if (lane == 0) {
                s_prefix = run;
                atomicExch(&state[b], (2u << 30) | (run + agg));
            }
        }
    }
    __syncthreads();

    int ex = (int)s_prefix + incl - s;     // exclusive prefix before this thread's 4 cells
    int4 vx;
    vx.x = ex;
    vx.y = ex + o0;
    vx.z = ex + o0 + o1;
    vx.w = ex + o0 + o1 + o2;
    *(int4*)&g_cellvox[c0] = vx;
    if (b == SCAN_BLOCKS - 1 && t == 1023) g_totvox = ex + o0 + o1 + o2 + o3;
}

// ---------------- emit: one warp per cell, stable order via index rank; fused tail ----------------
__global__ void k_emit(const float* __restrict__ pts, float* __restrict__ out) {
    int gw   = (blockIdx.x * blockDim.x + threadIdx.x) >> 5;
    int lane = threadIdx.x & 31;
    int w    = (threadIdx.x >> 5) & 7;
    __shared__ float4 sbuf4[8][40];   // 640 B staging per warp
    __shared__ int    sidx[8][32];

    // fused tail: zero voxels with no owner (no-op when totvox >= MAXV)
    if (gw < MAXV && gw >= g_totvox) {
        float4 z = make_float4(0.f, 0.f, 0.f, 0.f);
        float4* dst = (float4*)(out + (size_t)gw * (MAXP * NFEAT));
        for (int j = lane; j < 40; j += 32) dst[j] = z;
        if (lane == 0) {
            float* oc = out + OUT_COORD_OFF + (size_t)gw * 3;
            oc[0] = 0.f; oc[1] = 0.f; oc[2] = 0.f;
            out[OUT_NUM_OFF + gw] = 0.f;
        }
    }

    if (gw >= NCELLS) return;
    int cell = gw;
    int cnt = (int)g_dyn[cell];
    if (cnt == 0) return;
    int v = g_cellvox[cell];
    if (v >= MAXV) return;

    float* sb = (float*)sbuf4[w];
    int n;
    if (cnt <= MAXP) {
        n = cnt;
        float4 a, bb; int pidx;
        size_t base = (size_t)cell * MAXP * 2;
        if (lane < cnt) {
            a  = g_slot[base + (size_t)lane * 2];
            bb = g_slot[base + (size_t)lane * 2 + 1];
            pidx = __float_as_int(a.w);
        } else {
            pidx = 0x7fffffff;
        }
        int rank = 0;
        #pragma unroll
        for (int k = 0; k < 32; k++) {
            int o = __shfl_sync(0xffffffffu, pidx, k);
            rank += (o < pidx) ? 1 : 0;
        }
        // zero only the unused tail of staging
        for (int j = n * NFEAT + lane; j < MAXP * NFEAT; j += 32) sb[j] = 0.0f;
        __syncwarp();
        if (lane < cnt) {
            float* d = sb + rank * NFEAT;
            d[0] = a.x; d[1] = a.y; d[2] = a.z; d[3] = bb.x; d[4] = bb.y;
        }
        __syncwarp();
    } else {
        // overflow fallback (statistically never): first 32 points in original order,
        // cells re-derived from pts (no ptcell array needed)
        n = MAXP;
        if (lane == 0) {
            int m = 0;
            for (int j = 0; j < N_POINTS && m < MAXP; j++) {
                const float* p = pts + (size_t)j * NFEAT;
                int cx = (int)floorf((p[0] + 50.0f) * 4.0f);
                int cy = (int)floorf((p[1] + 50.0f) * 4.0f);
                int cz = (int)floorf((p[2] + 5.0f) * 0.125f);
                if (cx >= 0 && cx < GXD && cy >= 0 && cy < GYD && cz == 0 &&
                    cy * GXD + cx == cell) sidx[w][m++] = j;
            }
        }
        __syncwarp();
        int idx = sidx[w][lane];
        const float* p = pts + (size_t)idx * NFEAT;
        float* d = sb + lane * NFEAT;
        #pragma unroll
        for (int f = 0; f < NFEAT; f++) d[f] = p[f];
        __syncwarp();
    }

    // coalesced 640B write per voxel
    float4* dst = (float4*)(out + (size_t)v * (MAXP * NFEAT));
    #pragma unroll
    for (int j = lane; j < 40; j += 32) dst[j] = sbuf4[w][j];
    if (lane == 0) {
        int cy = cell / GXD, cx = cell - cy * GXD;
        float* oc = out + OUT_COORD_OFF + (size_t)v * 3;
        oc[0] = 0.0f;           // z
        oc[1] = (float)cy;      // y
        oc[2] = (float)cx;      // x
        out[OUT_NUM_OFF + v] = (float)n;
    }
}

extern "C" void kernel_launch(void* const* d_in, const int* in_sizes, int n_in,
                              void* d_out, int out_size) {
    const float* pts = (const float*)d_in[0];
    float* out = (float*)d_out;
    (void)in_sizes; (void)n_in; (void)out_size;

    void* dynptr = nullptr;
    cudaGetSymbolAddress(&dynptr, g_dyn);
    cudaMemsetAsync(dynptr, 0, sizeof(unsigned) * (NCELLS_PAD + SCAN_BLOCKS), 0);

    k_assign<<<(N_POINTS + 255) / 256, 256>>>(pts);
    k_scan  <<<SCAN_BLOCKS, 1024>>>();
    k_emit  <<<(NCELLS * 32 + 255) / 256, 256>>>(pts, out);
}

// round 7
// speedup vs baseline: 1.2607x; 1.2607x over previous
#include <cuda_runtime.h>
#include <stdint.h>

#define N_POINTS 1200000
#define NFEAT 5
#define GXD 400
#define GYD 400
#define NCELLS (GXD*GYD)          // 160000
#define NCELLS_PAD 163840         // 40 * 4096
#define MAXV 60000
#define MAXP 32
#define OUT_COORD_OFF (MAXV*MAXP*NFEAT)        // 9,600,000
#define OUT_NUM_OFF   (OUT_COORD_OFF + MAXV*3) // 9,780,000
#define SCAN_BLOCKS 40
#define CELLS_PER_BLOCK 4096       // 1024 threads * 4 cells
#define DYN_TOTAL (NCELLS_PAD + SCAN_BLOCKS)

// [0,NCELLS_PAD) = per-cell counts, then SCAN_BLOCKS lookback states.
// Zero-initialized at load; k_emit re-zeroes it each launch for the next replay.
__device__ unsigned g_dyn[DYN_TOTAL];
__device__ int      g_totvox;
__device__ unsigned g_voxlist[MAXV];                 // cell(18b) | min(cnt,16383)<<18
__device__ int      g_slotidx[(size_t)NCELLS * MAXP]; // point index per (cell, arrival-rank)

// ---------------- assign: 4 points/thread, stage index only ----------------
__global__ void k_assign(const float4* __restrict__ pts4) {
    int t = blockIdx.x * blockDim.x + threadIdx.x;
    if (t >= N_POINTS / 4) return;
    // 4 points = 80 bytes = 5 aligned float4 loads (16B loads at 16B offsets never split sectors)
    const float4* src = pts4 + (size_t)t * 5;
    float4 q0 = src[0], q1 = src[1], q2 = src[2], q3 = src[3], q4 = src[4];
    float f[20] = { q0.x,q0.y,q0.z,q0.w, q1.x,q1.y,q1.z,q1.w,
                    q2.x,q2.y,q2.z,q2.w, q3.x,q3.y,q3.z,q3.w,
                    q4.x,q4.y,q4.z,q4.w };
    int base = t * 4;
    #pragma unroll
    for (int k = 0; k < 4; k++) {
        float x = f[5*k], y = f[5*k+1], z = f[5*k+2];
        // exact: (v+50)*4 == (v-(-50))/0.25 ; (v+5)*0.125 == (v-(-5))/8
        int cx = (int)floorf((x + 50.0f) * 4.0f);
        int cy = (int)floorf((y + 50.0f) * 4.0f);
        int cz = (int)floorf((z + 5.0f) * 0.125f);
        if (cx >= 0 && cx < GXD && cy >= 0 && cy < GYD && cz == 0) {
            int cell = cy * GXD + cx;
            unsigned r = atomicAdd(&g_dyn[cell], 1u);
            if (r < MAXP) g_slotidx[(size_t)cell * MAXP + r] = base + k;
        }
    }
}

// ---------------- scan: single-wave decoupled lookback + voxel-list compaction ----------------
__global__ void __launch_bounds__(1024, 1) k_scan() {
    __shared__ int wsum[32];
    __shared__ unsigned s_prefix;
    unsigned* state = g_dyn + NCELLS_PAD;
    const int t = threadIdx.x, b = blockIdx.x;
    const int lane = t & 31, w = t >> 5;
    const int c0 = b * CELLS_PER_BLOCK + t * 4;

    uint4 c4 = *(const uint4*)&g_dyn[c0];
    int o0 = c4.x ? 1 : 0, o1 = c4.y ? 1 : 0, o2 = c4.z ? 1 : 0, o3 = c4.w ? 1 : 0;
    int s = o0 + o1 + o2 + o3;

    int x = s;
    #pragma unroll
    for (int o = 1; o < 32; o <<= 1) {
        int v = __shfl_up_sync(0xffffffffu, x, o);
        if (lane >= o) x += v;
    }
    if (lane == 31) wsum[w] = x;
    __syncthreads();
    if (w == 0) {
        int y = wsum[lane];
        #pragma unroll
        for (int o = 1; o < 32; o <<= 1) {
            int v = __shfl_up_sync(0xffffffffu, y, o);
            if (lane >= o) y += v;
        }
        wsum[lane] = y;
    }
    __syncthreads();
    int incl = x + (w ? wsum[w - 1] : 0);
    unsigned agg = (unsigned)wsum[31];

    if (t == 0) {
        if (b == 0) atomicExch(&state[0], (2u << 30) | agg);
        else        atomicExch(&state[b], (1u << 30) | agg);
    }
    if (w == 0) {
        if (b == 0) { if (lane == 0) s_prefix = 0; }
        else {
            unsigned run = 0;
            int j = b - 1 - lane;
            for (;;) {
                unsigned sv = (j >= 0) ? *(volatile unsigned*)&state[j] : (2u << 30);
                unsigned flag = sv >> 30;
                if (__all_sync(0xffffffffu, flag != 0u)) {
                    unsigned pm = __ballot_sync(0xffffffffu, flag >= 2u);
                    int fp = (pm != 0u) ? (__ffs(pm) - 1) : -1;
                    unsigned contrib = (fp < 0 || lane <= fp) ? (sv & 0x3FFFFFFFu) : 0u;
                    #pragma unroll
                    for (int o = 16; o; o >>= 1)
                        contrib += __shfl_down_sync(0xffffffffu, contrib, o);
                    contrib = __shfl_sync(0xffffffffu, contrib, 0);
                    run += contrib;
                    if (fp >= 0) break;
                    j -= 32;
                }
            }
            if (lane == 0) {
                s_prefix = run;
                atomicExch(&state[b], (2u << 30) | (run + agg));
            }
        }
    }
    __syncthreads();

    int e = (int)s_prefix + incl - s;   // exclusive prefix of occupancy before cell c0
    if (o0) { if (e < MAXV) g_voxlist[e] = (unsigned)(c0+0) | (umin(c4.x, 16383u) << 18); e++; }
    if (o1) { if (e < MAXV) g_voxlist[e] = (unsigned)(c0+1) | (umin(c4.y, 16383u) << 18); e++; }
    if (o2) { if (e < MAXV) g_voxlist[e] = (unsigned)(c0+2) | (umin(c4.z, 16383u) << 18); e++; }
    if (o3) { if (e < MAXV) g_voxlist[e] = (unsigned)(c0+3) | (umin(c4.w, 16383u) << 18); e++; }
    if (b == SCAN_BLOCKS - 1 && t == 1023) g_totvox = e;
}

// ---------------- emit: one warp per OUTPUT voxel; all warps productive ----------------
__global__ void k_emit(const float* __restrict__ pts, float* __restrict__ out) {
    int gid  = blockIdx.x * blockDim.x + threadIdx.x;
    int gw   = gid >> 5;                  // voxel index
    int lane = threadIdx.x & 31;
    int w    = (threadIdx.x >> 5) & 7;
    __shared__ float sbuf[8][160];
    __shared__ int   sidx[8][32];

    // reset counters + lookback state for the next replay (globals start zeroed at load)
    if (gid < DYN_TOTAL) g_dyn[gid] = 0;

    if (gw >= MAXV) return;
    int tv = g_totvox;
    if (gw >= tv) {
        // zero-fill unowned voxel (no-op when totvox >= MAXV)
        float4 z = make_float4(0.f, 0.f, 0.f, 0.f);
        float4* dst = (float4*)(out + (size_t)gw * (MAXP * NFEAT));
        for (int j = lane; j < 40; j += 32) dst[j] = z;
        if (lane == 0) {
            float* oc = out + OUT_COORD_OFF + (size_t)gw * 3;
            oc[0] = 0.f; oc[1] = 0.f; oc[2] = 0.f;
            out[OUT_NUM_OFF + gw] = 0.f;
        }
        return;
    }

    unsigned packed = g_voxlist[gw];
    int cell = (int)(packed & 0x3FFFFu);
    int cnt  = (int)(packed >> 18);
    float f0, f1, f2, f3, f4;
    int slot, n;

    if (cnt <= MAXP) {
        n = cnt;
        int idx = (lane < cnt) ? g_slotidx[(size_t)cell * MAXP + lane] : 0x7fffffff;
        int rank = 0;
        #pragma unroll
        for (int k = 0; k < 32; k++) {
            int o = __shfl_sync(0xffffffffu, idx, k);
            rank += (o < idx) ? 1 : 0;
        }
        slot = (lane < cnt) ? rank : lane;   // ranks tile [0,cnt), idle lanes tile [cnt,32)
        if (lane < cnt) {
            const float* p = pts + (size_t)idx * NFEAT;
            f0 = p[0]; f1 = p[1]; f2 = p[2]; f3 = p[3]; f4 = p[4];
        } else {
            f0 = f1 = f2 = f3 = f4 = 0.0f;
        }
    } else {
        // overflow fallback (statistically never): first 32 matches scanning ascending j
        // are exactly the 32 smallest original indices, already in order.
        n = MAXP;
        slot = lane;
        if (lane == 0) {
            int m = 0;
            for (int j = 0; j < N_POINTS && m < MAXP; j++) {
                const float* p = pts + (size_t)j * NFEAT;
                int cx = (int)floorf((p[0] + 50.0f) * 4.0f);
                int cy = (int)floorf((p[1] + 50.0f) * 4.0f);
                int cz = (int)floorf((p[2] + 5.0f) * 0.125f);
                if (cx >= 0 && cx < GXD && cy >= 0 && cy < GYD && cz == 0 &&
                    cy * GXD + cx == cell) sidx[w][m++] = j;
            }
        }
        __syncwarp();
        int idx = sidx[w][lane];
        const float* p = pts + (size_t)idx * NFEAT;
        f0 = p[0]; f1 = p[1]; f2 = p[2]; f3 = p[3]; f4 = p[4];
    }

    // stage ranked points in smem (stride 5 is coprime to 32 -> conflict-free),
    // then write the 640B voxel row coalesced.
    float* sb = sbuf[w];
    float* d = sb + slot * NFEAT;
    d[0] = f0; d[1] = f1; d[2] = f2; d[3] = f3; d[4] = f4;
    __syncwarp();
    float4* s4 = (float4*)sb;
    float4* dst = (float4*)(out + (size_t)gw * (MAXP * NFEAT));
    #pragma unroll
    for (int j = lane; j < 40; j += 32) dst[j] = s4[j];
    if (lane == 0) {
        int cy = cell / GXD, cx = cell - cy * GXD;
        float* oc = out + OUT_COORD_OFF + (size_t)gw * 3;
        oc[0] = 0.0f;           // z
        oc[1] = (float)cy;      // y
        oc[2] = (float)cx;      // x
        out[OUT_NUM_OFF + gw] = (float)n;
    }
}

extern "C" void kernel_launch(void* const* d_in, const int* in_sizes, int n_in,
                              void* d_out, int out_size) {
    const float* pts = (const float*)d_in[0];
    float* out = (float*)d_out;
    (void)in_sizes; (void)n_in; (void)out_size;

    k_assign<<<(N_POINTS / 4 + 255) / 256, 256>>>((const float4*)pts);
    k_scan  <<<SCAN_BLOCKS, 1024>>>();
    k_emit  <<<(MAXV * 32) / 256, 256>>>(pts, out);
}

// round 8
// speedup vs baseline: 1.7245x; 1.3679x over previous
#include <cuda_runtime.h>
#include <stdint.h>

#define N_POINTS 1200000
#define NFEAT 5
#define GXD 400
#define GYD 400
#define NCELLS (GXD*GYD)          // 160000
#define NCELLS_PAD 163840         // 40 * 4096
#define MAXV 60000
#define MAXP 32
#define OUT_COORD_OFF (MAXV*MAXP*NFEAT)        // 9,600,000
#define OUT_NUM_OFF   (OUT_COORD_OFF + MAXV*3) // 9,780,000
#define SCAN_BLOCKS 40
#define CELLS_PER_BLOCK 4096       // 1024 threads * 4 cells
#define DYN_TOTAL (NCELLS_PAD + SCAN_BLOCKS)
#define PPT 8                      // points per thread in assign

// [0,NCELLS_PAD) = per-cell counts, then SCAN_BLOCKS lookback states.
// Zero-initialized at load; k_emit re-zeroes it each launch for the next replay.
__device__ unsigned g_dyn[DYN_TOTAL];
__device__ int      g_totvox;
__device__ unsigned g_voxlist[MAXV];                 // cell(18b) | min(cnt,16383)<<18
__device__ int      g_slotidx[(size_t)NCELLS * MAXP]; // point index per (cell, arrival-rank)

// ---------------- assign: 8 points/thread, stage index only ----------------
__global__ void k_assign(const float4* __restrict__ pts4) {
    int t = blockIdx.x * blockDim.x + threadIdx.x;
    if (t >= N_POINTS / PPT) return;
    // 8 points = 160 bytes = 10 aligned float4 loads, all independent (MLP=10)
    const float4* src = pts4 + (size_t)t * 10;
    float4 q0 = src[0], q1 = src[1], q2 = src[2], q3 = src[3], q4 = src[4];
    float4 q5 = src[5], q6 = src[6], q7 = src[7], q8 = src[8], q9 = src[9];
    float f[40] = { q0.x,q0.y,q0.z,q0.w, q1.x,q1.y,q1.z,q1.w,
                    q2.x,q2.y,q2.z,q2.w, q3.x,q3.y,q3.z,q3.w,
                    q4.x,q4.y,q4.z,q4.w, q5.x,q5.y,q5.z,q5.w,
                    q6.x,q6.y,q6.z,q6.w, q7.x,q7.y,q7.z,q7.w,
                    q8.x,q8.y,q8.z,q8.w, q9.x,q9.y,q9.z,q9.w };
    int base = t * PPT;
    int cellv[PPT];
    #pragma unroll
    for (int k = 0; k < PPT; k++) {
        float x = f[5*k], y = f[5*k+1], z = f[5*k+2];
        // exact: (v+50)*4 == (v-(-50))/0.25 ; (v+5)*0.125 == (v-(-5))/8
        int cx = (int)floorf((x + 50.0f) * 4.0f);
        int cy = (int)floorf((y + 50.0f) * 4.0f);
        int cz = (int)floorf((z + 5.0f) * 0.125f);
        cellv[k] = (cx >= 0 && cx < GXD && cy >= 0 && cy < GYD && cz == 0)
                   ? (cy * GXD + cx) : -1;
    }
    #pragma unroll
    for (int k = 0; k < PPT; k++) {
        if (cellv[k] >= 0) {
            unsigned r = atomicAdd(&g_dyn[cellv[k]], 1u);
            if (r < MAXP) g_slotidx[(size_t)cellv[k] * MAXP + r] = base + k;
        }
    }
}

// ---------------- scan: single-wave decoupled lookback + voxel-list compaction ----------------
__global__ void __launch_bounds__(1024, 1) k_scan() {
    __shared__ int wsum[32];
    __shared__ unsigned s_prefix;
    unsigned* state = g_dyn + NCELLS_PAD;
    const int t = threadIdx.x, b = blockIdx.x;
    const int lane = t & 31, w = t >> 5;
    const int c0 = b * CELLS_PER_BLOCK + t * 4;

    uint4 c4 = *(const uint4*)&g_dyn[c0];
    int o0 = c4.x ? 1 : 0, o1 = c4.y ? 1 : 0, o2 = c4.z ? 1 : 0, o3 = c4.w ? 1 : 0;
    int s = o0 + o1 + o2 + o3;

    int x = s;
    #pragma unroll
    for (int o = 1; o < 32; o <<= 1) {
        int v = __shfl_up_sync(0xffffffffu, x, o);
        if (lane >= o) x += v;
    }
    if (lane == 31) wsum[w] = x;
    __syncthreads();
    if (w == 0) {
        int y = wsum[lane];
        #pragma unroll
        for (int o = 1; o < 32; o <<= 1) {
            int v = __shfl_up_sync(0xffffffffu, y, o);
            if (lane >= o) y += v;
        }
        wsum[lane] = y;
    }
    __syncthreads();
    int incl = x + (w ? wsum[w - 1] : 0);
    unsigned agg = (unsigned)wsum[31];

    if (t == 0) {
        if (b == 0) atomicExch(&state[0], (2u << 30) | agg);
        else        atomicExch(&state[b], (1u << 30) | agg);
    }
    if (w == 0) {
        if (b == 0) { if (lane == 0) s_prefix = 0; }
        else {
            unsigned run = 0;
            int j = b - 1 - lane;
            for (;;) {
                unsigned sv = (j >= 0) ? *(volatile unsigned*)&state[j] : (2u << 30);
                unsigned flag = sv >> 30;
                if (__all_sync(0xffffffffu, flag != 0u)) {
                    unsigned pm = __ballot_sync(0xffffffffu, flag >= 2u);
                    int fp = (pm != 0u) ? (__ffs(pm) - 1) : -1;
                    unsigned contrib = (fp < 0 || lane <= fp) ? (sv & 0x3FFFFFFFu) : 0u;
                    #pragma unroll
                    for (int o = 16; o; o >>= 1)
                        contrib += __shfl_down_sync(0xffffffffu, contrib, o);
                    contrib = __shfl_sync(0xffffffffu, contrib, 0);
                    run += contrib;
                    if (fp >= 0) break;
                    j -= 32;
                }
            }
            if (lane == 0) {
                s_prefix = run;
                atomicExch(&state[b], (2u << 30) | (run + agg));
            }
        }
    }
    __syncthreads();

    int e = (int)s_prefix + incl - s;   // exclusive prefix of occupancy before cell c0
    if (o0) { if (e < MAXV) g_voxlist[e] = (unsigned)(c0+0) | (umin(c4.x, 16383u) << 18); e++; }
    if (o1) { if (e < MAXV) g_voxlist[e] = (unsigned)(c0+1) | (umin(c4.y, 16383u) << 18); e++; }
    if (o2) { if (e < MAXV) g_voxlist[e] = (unsigned)(c0+2) | (umin(c4.z, 16383u) << 18); e++; }
    if (o3) { if (e < MAXV) g_voxlist[e] = (unsigned)(c0+3) | (umin(c4.w, 16383u) << 18); e++; }
    if (b == SCAN_BLOCKS - 1 && t == 1023) g_totvox = e;
}

// ---------------- emit: one warp per OUTPUT voxel; 2xLDG.128 gather ----------------
__global__ void __launch_bounds__(256) k_emit(const float* __restrict__ pts,
                                              float* __restrict__ out) {
    int gid  = blockIdx.x * blockDim.x + threadIdx.x;
    int gw   = gid >> 5;                  // voxel index
    int lane = threadIdx.x & 31;
    int w    = (threadIdx.x >> 5) & 7;
    __shared__ float sbuf[8][160];
    __shared__ int   sidx[8][32];

    // reset counters + lookback state for the next replay (globals start zeroed at load)
    if (gid < DYN_TOTAL) g_dyn[gid] = 0;

    if (gw >= MAXV) return;
    int tv = g_totvox;
    if (gw >= tv) {
        // zero-fill unowned voxel (no-op when totvox >= MAXV)
        float4 z = make_float4(0.f, 0.f, 0.f, 0.f);
        float4* dst = (float4*)(out + (size_t)gw * (MAXP * NFEAT));
        for (int j = lane; j < 40; j += 32) dst[j] = z;
        if (lane == 0) {
            float* oc = out + OUT_COORD_OFF + (size_t)gw * 3;
            oc[0] = 0.f; oc[1] = 0.f; oc[2] = 0.f;
            out[OUT_NUM_OFF + gw] = 0.f;
        }
        return;
    }

    unsigned packed = g_voxlist[gw];
    int cell = (int)(packed & 0x3FFFFu);
    int cnt  = (int)(packed >> 18);
    float f0 = 0.f, f1 = 0.f, f2 = 0.f, f3 = 0.f, f4 = 0.f;
    int slot, n;

    if (cnt <= MAXP) {
        n = cnt;
        int idx = (lane < cnt) ? g_slotidx[(size_t)cell * MAXP + lane] : 0x7fffffff;
        int rank = 0;
        #pragma unroll
        for (int k = 0; k < 32; k++) {
            int o = __shfl_sync(0xffffffffu, idx, k);
            rank += (o < idx) ? 1 : 0;
        }
        slot = (lane < cnt) ? rank : lane;   // ranks tile [0,cnt), idle lanes tile [cnt,32)
        if (lane < cnt) {
            // point row = 20B at byte offset 20*idx; always inside the two aligned
            // 16B words starting at float4 index (5*idx)>>2 (20i mod 16 <= 12).
            const float4* p4 = (const float4*)pts;
            int w0  = (5 * idx) >> 2;
            int off = idx & 3;               // rotation: 5i mod 4 == i mod 4
            float4 a = __ldg(&p4[w0]);
            float4 b = __ldg(&p4[w0 + 1]);
            f0 = off==0 ? a.x : off==1 ? a.y : off==2 ? a.z : a.w;
            f1 = off==0 ? a.y : off==1 ? a.z : off==2 ? a.w : b.x;
            f2 = off==0 ? a.z : off==1 ? a.w : off==2 ? b.x : b.y;
            f3 = off==0 ? a.w : off==1 ? b.x : off==2 ? b.y : b.z;
            f4 = off==0 ? b.x : off==1 ? b.y : off==2 ? b.z : b.w;
        }
    } else {
        // overflow fallback (statistically never): first 32 matches scanning ascending j
        // are exactly the 32 smallest original indices, already in order.
        n = MAXP;
        slot = lane;
        if (lane == 0) {
            int m = 0;
            for (int j = 0; j < N_POINTS && m < MAXP; j++) {
                const float* p = pts + (size_t)j * NFEAT;
                int cx = (int)floorf((p[0] + 50.0f) * 4.0f);
                int cy = (int)floorf((p[1] + 50.0f) * 4.0f);
                int cz = (int)floorf((p[2] + 5.0f) * 0.125f);
                if (cx >= 0 && cx < GXD && cy >= 0 && cy < GYD && cz == 0 &&
                    cy * GXD + cx == cell) sidx[w][m++] = j;
            }
        }
        __syncwarp();
        int idx = sidx[w][lane];
        const float* p = pts + (size_t)idx * NFEAT;
        f0 = p[0]; f1 = p[1]; f2 = p[2]; f3 = p[3]; f4 = p[4];
    }

    // stage ranked points in smem (stride 5 is coprime to 32 -> conflict-free),
    // then write the 640B voxel row coalesced.
    float* sb = sbuf[w];
    float* d = sb + slot * NFEAT;
    d[0] = f0; d[1] = f1; d[2] = f2; d[3] = f3; d[4] = f4;
    __syncwarp();
    float4* s4 = (float4*)sb;
    float4* dst = (float4*)(out + (size_t)gw * (MAXP * NFEAT));
    #pragma unroll
    for (int j = lane; j < 40; j += 32) dst[j] = s4[j];
    if (lane == 0) {
        int cy = cell / GXD, cx = cell - cy * GXD;
        float* oc = out + OUT_COORD_OFF + (size_t)gw * 3;
        oc[0] = 0.0f;           // z
        oc[1] = (float)cy;      // y
        oc[2] = (float)cx;      // x
        out[OUT_NUM_OFF + gw] = (float)n;
    }
}

extern "C" void kernel_launch(void* const* d_in, const int* in_sizes, int n_in,
                              void* d_out, int out_size) {
    const float* pts = (const float*)d_in[0];
    float* out = (float*)d_out;
    (void)in_sizes; (void)n_in; (void)out_size;

    k_assign<<<(N_POINTS / PPT + 255) / 256, 256>>>((const float4*)pts);
    k_scan  <<<SCAN_BLOCKS, 1024>>>();
    k_emit  <<<(MAXV * 32) / 256, 256>>>(pts, out);
}

// round 9
// speedup vs baseline: 1.8235x; 1.0574x over previous
#include <cuda_runtime.h>
#include <stdint.h>

#define N_POINTS 1200000
#define NFEAT 5
#define GXD 400
#define GYD 400
#define NCELLS (GXD*GYD)          // 160000
#define NCELLS_PAD 163840         // 40 * 4096
#define MAXV 60000
#define MAXP 32
#define OUT_COORD_OFF (MAXV*MAXP*NFEAT)        // 9,600,000
#define OUT_NUM_OFF   (OUT_COORD_OFF + MAXV*3) // 9,780,000
#define SCAN_BLOCKS 40
#define CELLS_PER_BLOCK 4096       // 1024 threads * 4 cells
#define DYN_TOTAL (NCELLS_PAD + SCAN_BLOCKS)
#define PPT 8                      // points per thread in assign

// [0,NCELLS_PAD) = per-cell counts, then SCAN_BLOCKS lookback states.
// Zero-initialized at load; k_emit re-zeroes it each launch for the next replay.
__device__ unsigned g_dyn[DYN_TOTAL];
__device__ int      g_totvox;
__device__ unsigned g_voxlist[MAXV];                 // cell(18b) | min(cnt,16383)<<18
__device__ int      g_slotidx[(size_t)NCELLS * MAXP]; // point index per (cell, arrival-rank)

__device__ __forceinline__ int cell_of(float x, float y, float z) {
    // exact: (v+50)*4 == (v-(-50))/0.25 ; (v+5)*0.125 == (v-(-5))/8
    int cx = (int)floorf((x + 50.0f) * 4.0f);
    int cy = (int)floorf((y + 50.0f) * 4.0f);
    int cz = (int)floorf((z + 5.0f) * 0.125f);
    return (cx >= 0 && cx < GXD && cy >= 0 && cy < GYD && cz == 0)
           ? (cy * GXD + cx) : -1;
}

// ---------------- assign: 8 points/thread, no local array (no spills) ----------------
__global__ void __launch_bounds__(256) k_assign(const float4* __restrict__ pts4) {
    int t = blockIdx.x * blockDim.x + threadIdx.x;
    if (t >= N_POINTS / PPT) return;
    // 8 points = 160 bytes = 10 aligned float4 loads, all independent (MLP=10)
    const float4* src = pts4 + (size_t)t * 10;
    float4 q0 = src[0], q1 = src[1], q2 = src[2], q3 = src[3], q4 = src[4];
    float4 q5 = src[5], q6 = src[6], q7 = src[7], q8 = src[8], q9 = src[9];
    // point k occupies floats [5k,5k+5); xyz = components 5k..5k+2 (static mapping)
    int c0 = cell_of(q0.x, q0.y, q0.z);
    int c1 = cell_of(q1.y, q1.z, q1.w);
    int c2 = cell_of(q2.z, q2.w, q3.x);
    int c3 = cell_of(q3.w, q4.x, q4.y);
    int c4 = cell_of(q5.x, q5.y, q5.z);
    int c5 = cell_of(q6.y, q6.z, q6.w);
    int c6 = cell_of(q7.z, q7.w, q8.x);
    int c7 = cell_of(q8.w, q9.x, q9.y);
    int base = t * PPT;
    int cellv[PPT] = { c0, c1, c2, c3, c4, c5, c6, c7 };
    #pragma unroll
    for (int k = 0; k < PPT; k++) {
        if (cellv[k] >= 0) {
            unsigned r = atomicAdd(&g_dyn[cellv[k]], 1u);
            if (r < MAXP) g_slotidx[(size_t)cellv[k] * MAXP + r] = base + k;
        }
    }
}

// ---------------- scan: single-wave decoupled lookback + voxel-list compaction ----------------
__global__ void __launch_bounds__(1024, 1) k_scan() {
    __shared__ int wsum[32];
    __shared__ unsigned s_prefix;
    unsigned* state = g_dyn + NCELLS_PAD;
    const int t = threadIdx.x, b = blockIdx.x;
    const int lane = t & 31, w = t >> 5;
    const int c0 = b * CELLS_PER_BLOCK + t * 4;

    uint4 c4 = *(const uint4*)&g_dyn[c0];
    int o0 = c4.x ? 1 : 0, o1 = c4.y ? 1 : 0, o2 = c4.z ? 1 : 0, o3 = c4.w ? 1 : 0;
    int s = o0 + o1 + o2 + o3;

    int x = s;
    #pragma unroll
    for (int o = 1; o < 32; o <<= 1) {
        int v = __shfl_up_sync(0xffffffffu, x, o);
        if (lane >= o) x += v;
    }
    if (lane == 31) wsum[w] = x;
    __syncthreads();
    if (w == 0) {
        int y = wsum[lane];
        #pragma unroll
        for (int o = 1; o < 32; o <<= 1) {
            int v = __shfl_up_sync(0xffffffffu, y, o);
            if (lane >= o) y += v;
        }
        wsum[lane] = y;
    }
    __syncthreads();
    int incl = x + (w ? wsum[w - 1] : 0);
    unsigned agg = (unsigned)wsum[31];

    if (t == 0) {
        if (b == 0) atomicExch(&state[0], (2u << 30) | agg);
        else        atomicExch(&state[b], (1u << 30) | agg);
    }
    if (w == 0) {
        if (b == 0) { if (lane == 0) s_prefix = 0; }
        else {
            unsigned run = 0;
            int j = b - 1 - lane;
            for (;;) {
                unsigned sv = (j >= 0) ? *(volatile unsigned*)&state[j] : (2u << 30);
                unsigned flag = sv >> 30;
                if (__all_sync(0xffffffffu, flag != 0u)) {
                    unsigned pm = __ballot_sync(0xffffffffu, flag >= 2u);
                    int fp = (pm != 0u) ? (__ffs(pm) - 1) : -1;
                    unsigned contrib = (fp < 0 || lane <= fp) ? (sv & 0x3FFFFFFFu) : 0u;
                    #pragma unroll
                    for (int o = 16; o; o >>= 1)
                        contrib += __shfl_down_sync(0xffffffffu, contrib, o);
                    contrib = __shfl_sync(0xffffffffu, contrib, 0);
                    run += contrib;
                    if (fp >= 0) break;
                    j -= 32;
                }
            }
            if (lane == 0) {
                s_prefix = run;
                atomicExch(&state[b], (2u << 30) | (run + agg));
            }
        }
    }
    __syncthreads();

    int e = (int)s_prefix + incl - s;   // exclusive prefix of occupancy before cell c0
    if (o0) { if (e < MAXV) g_voxlist[e] = (unsigned)(c0+0) | (umin(c4.x, 16383u) << 18); e++; }
    if (o1) { if (e < MAXV) g_voxlist[e] = (unsigned)(c0+1) | (umin(c4.y, 16383u) << 18); e++; }
    if (o2) { if (e < MAXV) g_voxlist[e] = (unsigned)(c0+2) | (umin(c4.z, 16383u) << 18); e++; }
    if (o3) { if (e < MAXV) g_voxlist[e] = (unsigned)(c0+3) | (umin(c4.w, 16383u) << 18); e++; }
    if (b == SCAN_BLOCKS - 1 && t == 1023) g_totvox = e;
}

// ---------------- emit: one warp per OUTPUT voxel; streaming stores ----------------
__global__ void __launch_bounds__(256) k_emit(const float* __restrict__ pts,
                                              float* __restrict__ out) {
    int gid  = blockIdx.x * blockDim.x + threadIdx.x;
    int gw   = gid >> 5;                  // voxel index
    int lane = threadIdx.x & 31;
    int w    = (threadIdx.x >> 5) & 7;
    __shared__ float sbuf[8][160];
    __shared__ int   sidx[8][32];

    // reset counters + lookback state for the next replay (globals start zeroed at load)
    if (gid < DYN_TOTAL) g_dyn[gid] = 0;

    if (gw >= MAXV) return;
    int tv = g_totvox;
    if (gw >= tv) {
        // zero-fill unowned voxel (no-op when totvox >= MAXV)
        float4 z = make_float4(0.f, 0.f, 0.f, 0.f);
        float4* dst = (float4*)(out + (size_t)gw * (MAXP * NFEAT));
        for (int j = lane; j < 40; j += 32) __stcs(&dst[j], z);
        if (lane == 0) {
            float* oc = out + OUT_COORD_OFF + (size_t)gw * 3;
            __stcs(&oc[0], 0.f); __stcs(&oc[1], 0.f); __stcs(&oc[2], 0.f);
            __stcs(&out[OUT_NUM_OFF + gw], 0.f);
        }
        return;
    }

    unsigned packed = __ldcs(&g_voxlist[gw]);
    int cell = (int)(packed & 0x3FFFFu);
    int cnt  = (int)(packed >> 18);
    float f0 = 0.f, f1 = 0.f, f2 = 0.f, f3 = 0.f, f4 = 0.f;
    int slot, n;

    if (cnt <= MAXP) {
        n = cnt;
        int idx = (lane < cnt) ? __ldcs(&g_slotidx[(size_t)cell * MAXP + lane]) : 0x7fffffff;
        int rank = 0;
        #pragma unroll
        for (int k = 0; k < 32; k++) {
            int o = __shfl_sync(0xffffffffu, idx, k);
            rank += (o < idx) ? 1 : 0;
        }
        slot = (lane < cnt) ? rank : lane;   // ranks tile [0,cnt), idle lanes tile [cnt,32)
        if (lane < cnt) {
            // point row = 20B at byte offset 20*idx; always inside the two aligned
            // 16B words starting at float4 index (5*idx)>>2 (20i mod 16 <= 12).
            const float4* p4 = (const float4*)pts;
            int w0  = (5 * idx) >> 2;
            int off = idx & 3;               // rotation: 5i mod 4 == i mod 4
            float4 a = __ldg(&p4[w0]);
            float4 b = __ldg(&p4[w0 + 1]);
            f0 = off==0 ? a.x : off==1 ? a.y : off==2 ? a.z : a.w;
            f1 = off==0 ? a.y : off==1 ? a.z : off==2 ? a.w : b.x;
            f2 = off==0 ? a.z : off==1 ? a.w : off==2 ? b.x : b.y;
            f3 = off==0 ? a.w : off==1 ? b.x : off==2 ? b.y : b.z;
            f4 = off==0 ? b.x : off==1 ? b.y : off==2 ? b.z : b.w;
        }
    } else {
        // overflow fallback (statistically never): first 32 matches scanning ascending j
        // are exactly the 32 smallest original indices, already in order.
        n = MAXP;
        slot = lane;
        if (lane == 0) {
            int m = 0;
            for (int j = 0; j < N_POINTS && m < MAXP; j++) {
                const float* p = pts + (size_t)j * NFEAT;
                int cx = (int)floorf((p[0] + 50.0f) * 4.0f);
                int cy = (int)floorf((p[1] + 50.0f) * 4.0f);
                int cz = (int)floorf((p[2] + 5.0f) * 0.125f);
                if (cx >= 0 && cx < GXD && cy >= 0 && cy < GYD && cz == 0 &&
                    cy * GXD + cx == cell) sidx[w][m++] = j;
            }
        }
        __syncwarp();
        int idx = sidx[w][lane];
        const float* p = pts + (size_t)idx * NFEAT;
        f0 = p[0]; f1 = p[1]; f2 = p[2]; f3 = p[3]; f4 = p[4];
    }

    // stage ranked points in smem (stride 5 is coprime to 32 -> conflict-free),
    // then write the 640B voxel row coalesced with streaming stores.
    float* sb = sbuf[w];
    float* d = sb + slot * NFEAT;
    d[0] = f0; d[1] = f1; d[2] = f2; d[3] = f3; d[4] = f4;
    __syncwarp();
    float4* s4 = (float4*)sb;
    float4* dst = (float4*)(out + (size_t)gw * (MAXP * NFEAT));
    #pragma unroll
    for (int j = lane; j < 40; j += 32) __stcs(&dst[j], s4[j]);
    if (lane == 0) {
        int cy = cell / GXD, cx = cell - cy * GXD;
        float* oc = out + OUT_COORD_OFF + (size_t)gw * 3;
        __stcs(&oc[0], 0.0f);           // z
        __stcs(&oc[1], (float)cy);      // y
        __stcs(&oc[2], (float)cx);      // x
        __stcs(&out[OUT_NUM_OFF + gw], (float)n);
    }
}

extern "C" void kernel_launch(void* const* d_in, const int* in_sizes, int n_in,
                              void* d_out, int out_size) {
    const float* pts = (const float*)d_in[0];
    float* out = (float*)d_out;
    (void)in_sizes; (void)n_in; (void)out_size;

    k_assign<<<(N_POINTS / PPT + 255) / 256, 256>>>((const float4*)pts);
    k_scan  <<<SCAN_BLOCKS, 1024>>>();
    k_emit  <<<(MAXV * 32) / 256, 256>>>(pts, out);
}